// round 2
// baseline (speedup 1.0000x reference)
#include <cuda_runtime.h>
#include <cuda_bf16.h>

// Problem constants (fixed by reference setup_inputs)
#define N_MAX   (384*384)     // 147456 pixels
#define A_FEAT  32            // features per pixel
#define K_NBR   48            // neighbors per pixel
#define EPSV    1e-9f

// Scratch: row-major feature table UU[N][32], 128B-aligned rows.
__device__ __align__(128) float g_UU[N_MAX * A_FEAT];

// ---------------------------------------------------------------------------
// Kernel 1: transpose input1 [32, N] -> g_UU [N, 32]
// ---------------------------------------------------------------------------
__global__ void transpose_kernel(const float* __restrict__ in, int N) {
    __shared__ float tile[32][33];
    const int n0 = blockIdx.x * 32;
    const int tx = threadIdx.x;      // 0..31
    const int ty = threadIdx.y;      // 0..7
#pragma unroll
    for (int i = 0; i < 32; i += 8) {
        tile[ty + i][tx] = in[(size_t)(ty + i) * N + n0 + tx];
    }
    __syncthreads();
#pragma unroll
    for (int i = 0; i < 32; i += 8) {
        g_UU[(size_t)(n0 + ty + i) * A_FEAT + tx] = tile[tx][ty + i];
    }
}

// ---------------------------------------------------------------------------
// Kernel 2: per-pixel distance + softmax.
// 8 lanes per pixel: lane gl owns float4 u[4*gl .. 4*gl+3].
// For each of 48 neighbors: coalesced float4 gather (4x 128B lines per
// 32-lane warp instruction), 3-stage xor-butterfly (width 8) reduction.
// ---------------------------------------------------------------------------
__global__ void __launch_bounds__(256) dist_softmax_kernel(
        const int* __restrict__ idx,       // [N, 48] int32
        float* __restrict__ out, int N) {
    const int tid = blockIdx.x * blockDim.x + threadIdx.x;
    const int j  = tid >> 3;        // pixel
    const int gl = tid & 7;         // lane within 8-lane group
    if (j >= N) return;

    const float4* __restrict__ UU4 = reinterpret_cast<const float4*>(g_UU);

    // own feature chunk
    const float4 u = UU4[j * 8 + gl];

    // preload the 6 neighbor indices this lane is responsible for (k = t*8+gl)
    int myidx[6];
    const int* __restrict__ idx_row = idx + (size_t)j * K_NBR;
#pragma unroll
    for (int t = 0; t < 6; t++) {
        int v = idx_row[t * 8 + gl];
        // defensive clamp (indices are in [0,N) per reference; this converts a
        // hypothetical dtype misread into a wrong answer instead of a crash)
        myidx[t] = min(max(v, 0), N - 1);
    }

    float D[6];
#pragma unroll
    for (int t = 0; t < 6; t++) {
#pragma unroll
        for (int s = 0; s < 8; s++) {
            const int nk = __shfl_sync(0xffffffffu, myidx[t], s, 8);
            const float4 v = UU4[nk * 8 + gl];
            const float d0 = u.x - v.x;
            const float d1 = u.y - v.y;
            const float d2 = u.z - v.z;
            const float d3 = u.w - v.w;
            float acc = d0 * d0;
            acc = fmaf(d1, d1, acc);
            acc = fmaf(d2, d2, acc);
            acc = fmaf(d3, d3, acc);
            // reduce across the 8 lanes of the group
            acc += __shfl_xor_sync(0xffffffffu, acc, 1, 8);
            acc += __shfl_xor_sync(0xffffffffu, acc, 2, 8);
            acc += __shfl_xor_sync(0xffffffffu, acc, 4, 8);
            if (s == gl) D[t] = acc;   // lane gl keeps neighbor k = t*8+gl
        }
    }

    // D_k = -sqrt(mean + eps)
#pragma unroll
    for (int t = 0; t < 6; t++) {
        D[t] = -sqrtf(fmaf(D[t], 1.0f / 32.0f, EPSV));
    }

    // softmax over 48 (6 local values x 8 lanes)
    float m = D[0];
#pragma unroll
    for (int t = 1; t < 6; t++) m = fmaxf(m, D[t]);
    m = fmaxf(m, __shfl_xor_sync(0xffffffffu, m, 1, 8));
    m = fmaxf(m, __shfl_xor_sync(0xffffffffu, m, 2, 8));
    m = fmaxf(m, __shfl_xor_sync(0xffffffffu, m, 4, 8));

    float e[6];
    float ssum = 0.0f;
#pragma unroll
    for (int t = 0; t < 6; t++) {
        e[t] = __expf(D[t] - m);
        ssum += e[t];
    }
    ssum += __shfl_xor_sync(0xffffffffu, ssum, 1, 8);
    ssum += __shfl_xor_sync(0xffffffffu, ssum, 2, 8);
    ssum += __shfl_xor_sync(0xffffffffu, ssum, 4, 8);

    const float inv = 1.0f / ssum;
    float* __restrict__ orow = out + (size_t)j * K_NBR;
#pragma unroll
    for (int t = 0; t < 6; t++) {
        orow[t * 8 + gl] = e[t] * inv;
    }
}

// ---------------------------------------------------------------------------
extern "C" void kernel_launch(void* const* d_in, const int* in_sizes, int n_in,
                              void* d_out, int out_size) {
    const float* input1 = (const float*)d_in[0];   // [32, N] fp32
    const int*   input2 = (const int*)d_in[1];     // [N, 48] int32 (JAX x64 off)
    float*       out    = (float*)d_out;           // [N, 48] fp32

    const int N = in_sizes[0] / A_FEAT;   // 147456

    // 1) transpose to row-major feature table
    {
        dim3 blk(32, 8);
        dim3 grd(N / 32);
        transpose_kernel<<<grd, blk>>>(input1, N);
    }
    // 2) distances + softmax: 8 threads per pixel
    {
        const int threads = 256;
        const long long total = (long long)N * 8;
        const int blocks = (int)((total + threads - 1) / threads);
        dist_softmax_kernel<<<blocks, threads>>>(input2, out, N);
    }
}

// round 3
// speedup vs baseline: 1.0793x; 1.0793x over previous
#include <cuda_runtime.h>
#include <cuda_fp16.h>

// Problem constants (fixed by reference setup_inputs)
#define N_MAX   (384*384)     // 147456 pixels
#define A_FEAT  32            // features per pixel
#define K_NBR   48            // neighbors per pixel
#define EPSV    1e-9f

// Scratch: row-major fp16 feature table UU[N][32] (64B rows, 128B-aligned base).
__device__ __align__(128) __half g_UUh[N_MAX * A_FEAT];

// ---------------------------------------------------------------------------
// Kernel 1: transpose + compress input1 [32, N] fp32 -> g_UUh [N, 32] fp16
// ---------------------------------------------------------------------------
__global__ void transpose_kernel(const float* __restrict__ in, int N) {
    __shared__ float tile[32][33];
    const int n0 = blockIdx.x * 32;
    const int tx = threadIdx.x;      // 0..31
    const int ty = threadIdx.y;      // 0..7
#pragma unroll
    for (int i = 0; i < 32; i += 8) {
        tile[ty + i][tx] = in[(size_t)(ty + i) * N + n0 + tx];
    }
    __syncthreads();
#pragma unroll
    for (int i = 0; i < 32; i += 8) {
        g_UUh[(size_t)(n0 + ty + i) * A_FEAT + tx] = __float2half(tile[tx][ty + i]);
    }
}

// ---------------------------------------------------------------------------
// Kernel 2: per-pixel distance + softmax.
// 8 lanes per pixel: lane gl owns 4 fp16 features (8B) of the 64B row.
// Gather is one LDG.64 per lane-step; width-8 xor-butterfly reductions.
// ---------------------------------------------------------------------------
__global__ void __launch_bounds__(256) dist_softmax_kernel(
        const int* __restrict__ idx,       // [N, 48] int32
        float* __restrict__ out, int N) {
    const int tid = blockIdx.x * blockDim.x + threadIdx.x;
    const int j  = tid >> 3;        // pixel
    const int gl = tid & 7;         // lane within 8-lane group
    if (j >= N) return;

    const __half2* __restrict__ UUh2 = reinterpret_cast<const __half2*>(g_UUh);

    // own feature chunk: 4 halves -> 2x half2 -> fp32
    const int base_own = j * 16 + gl * 2;   // half2 units: row = 16 half2
    const float2 ua = __half22float2(UUh2[base_own + 0]);
    const float2 ub = __half22float2(UUh2[base_own + 1]);

    // preload the 6 neighbor indices this lane is responsible for (k = t*8+gl)
    int myidx[6];
    const int* __restrict__ idx_row = idx + (size_t)j * K_NBR;
#pragma unroll
    for (int t = 0; t < 6; t++) {
        int v = idx_row[t * 8 + gl];
        myidx[t] = min(max(v, 0), N - 1);   // defensive clamp
    }

    float D[6];
#pragma unroll
    for (int t = 0; t < 6; t++) {
#pragma unroll
        for (int s = 0; s < 8; s++) {
            const int nk = __shfl_sync(0xffffffffu, myidx[t], s, 8);
            // 8B gather: two half2 (one LDG.64)
            const uint2 raw = *reinterpret_cast<const uint2*>(&UUh2[nk * 16 + gl * 2]);
            const float2 va = __half22float2(*reinterpret_cast<const __half2*>(&raw.x));
            const float2 vb = __half22float2(*reinterpret_cast<const __half2*>(&raw.y));
            const float d0 = ua.x - va.x;
            const float d1 = ua.y - va.y;
            const float d2 = ub.x - vb.x;
            const float d3 = ub.y - vb.y;
            float acc = d0 * d0;
            acc = fmaf(d1, d1, acc);
            acc = fmaf(d2, d2, acc);
            acc = fmaf(d3, d3, acc);
            // reduce across the 8 lanes of the group
            acc += __shfl_xor_sync(0xffffffffu, acc, 1, 8);
            acc += __shfl_xor_sync(0xffffffffu, acc, 2, 8);
            acc += __shfl_xor_sync(0xffffffffu, acc, 4, 8);
            if (s == gl) D[t] = acc;   // lane gl keeps neighbor k = t*8+gl
        }
    }

    // D_k = -sqrt(mean + eps)
#pragma unroll
    for (int t = 0; t < 6; t++) {
        D[t] = -sqrtf(fmaf(D[t], 1.0f / 32.0f, EPSV));
    }

    // softmax over 48 (6 local values x 8 lanes)
    float m = D[0];
#pragma unroll
    for (int t = 1; t < 6; t++) m = fmaxf(m, D[t]);
    m = fmaxf(m, __shfl_xor_sync(0xffffffffu, m, 1, 8));
    m = fmaxf(m, __shfl_xor_sync(0xffffffffu, m, 2, 8));
    m = fmaxf(m, __shfl_xor_sync(0xffffffffu, m, 4, 8));

    float e[6];
    float ssum = 0.0f;
#pragma unroll
    for (int t = 0; t < 6; t++) {
        e[t] = __expf(D[t] - m);
        ssum += e[t];
    }
    ssum += __shfl_xor_sync(0xffffffffu, ssum, 1, 8);
    ssum += __shfl_xor_sync(0xffffffffu, ssum, 2, 8);
    ssum += __shfl_xor_sync(0xffffffffu, ssum, 4, 8);

    const float inv = 1.0f / ssum;
    float* __restrict__ orow = out + (size_t)j * K_NBR;
#pragma unroll
    for (int t = 0; t < 6; t++) {
        orow[t * 8 + gl] = e[t] * inv;
    }
}

// ---------------------------------------------------------------------------
extern "C" void kernel_launch(void* const* d_in, const int* in_sizes, int n_in,
                              void* d_out, int out_size) {
    const float* input1 = (const float*)d_in[0];   // [32, N] fp32
    const int*   input2 = (const int*)d_in[1];     // [N, 48] int32 (JAX x64 off)
    float*       out    = (float*)d_out;           // [N, 48] fp32

    const int N = in_sizes[0] / A_FEAT;   // 147456

    // 1) transpose + fp16 compress
    {
        dim3 blk(32, 8);
        dim3 grd(N / 32);
        transpose_kernel<<<grd, blk>>>(input1, N);
    }
    // 2) distances + softmax: 8 threads per pixel
    {
        const int threads = 256;
        const long long total = (long long)N * 8;
        const int blocks = (int)((total + threads - 1) / threads);
        dist_softmax_kernel<<<blocks, threads>>>(input2, out, N);
    }
}